// round 10
// baseline (speedup 1.0000x reference)
#include <cuda_runtime.h>
#include <cuda_fp16.h>
#include <math.h>
#include <stdint.h>

#define NN 50000
#define EE 800000
#define C0 32
#define C1 64
#define KP 25
#define KGRP 5
#define FIN 160
#define YSTRIDE (KP * 64)   // 1600
#define CSW 72              // C-staging stride in halfs (144 B)

// ---------------- scratch -----------------------------------------------------
__device__ __align__(16) __half g_Yh[(size_t)NN * YSTRIDE];  // 160 MB fp16
__device__ __align__(16) float  g_H1[(size_t)NN * 64];
__device__ __align__(16) float  g_H2[(size_t)NN * 64];
__device__ __align__(16) float  g_AGG[(size_t)NN * 64];
__device__ __align__(16) float  g_DEG[NN];                   // 1/max(deg,1) after recip
__device__ __align__(16) float4 g_B[EE];
__device__ int    g_K0[EE];
__device__ int    g_src[EE];
__device__ int    g_dst[EE];
__device__ int    g_CNT[NN];         // per-src histogram -> base offsets
__device__ int    g_OFF[NN];         // scatter cursors
__device__ __align__(16) int4   s_meta[EE];   // sorted {src,dst,k0,-}
__device__ __align__(16) float4 s_B[EE];      // sorted basis * 1/deg(dst)

// ---------------- init / prep / recip / scan / scatter -----------------------
__global__ void init_kernel() {
    int i = blockIdx.x * blockDim.x + threadIdx.x;
    if (i < NN * 64) g_AGG[i] = 0.0f;
    if (i < NN) { g_DEG[i] = 0.0f; g_CNT[i] = 0; }
}

__global__ void prep_kernel(const int* __restrict__ ei,
                            const float* __restrict__ ea) {
    int e = blockIdx.x * blockDim.x + threadIdx.x;
    if (e >= EE) return;
    int src = ei[e];
    int dst = ei[EE + e];
    g_src[e] = src;
    g_dst[e] = dst;
    atomicAdd(&g_DEG[dst], 1.0f);
    atomicAdd(&g_CNT[src], 1);
    float v0 = ea[2 * e + 0] * 4.0f;
    float v1 = ea[2 * e + 1] * 4.0f;
    float b0f = floorf(v0), b1f = floorf(v1);
    float f0 = v0 - b0f, f1 = v1 - b1f;
    int i0 = min((int)b0f, 3);
    int i1 = min((int)b1f, 3);
    g_K0[e] = i0 + 5 * i1;
    g_B[e] = make_float4((1.f - f0) * (1.f - f1),
                         f0 * (1.f - f1),
                         (1.f - f0) * f1,
                         f0 * f1);
}

__global__ void recip_kernel() {
    int i = blockIdx.x * blockDim.x + threadIdx.x;
    if (i < NN) g_DEG[i] = 1.0f / fmaxf(g_DEG[i], 1.0f);
}

// single-block exclusive scan over g_CNT (50000 bins); writes offsets to
// g_CNT (base) and g_OFF (cursor).
#define SCHUNK 49
__global__ void scan_kernel() {
    __shared__ int part[1024];
    int t = threadIdx.x;
    int lo = t * SCHUNK, hi = min(lo + SCHUNK, NN);
    int s = 0;
    for (int i = lo; i < hi; i++) s += g_CNT[i];
    part[t] = s;
    __syncthreads();
    for (int off = 1; off < 1024; off <<= 1) {
        int v = (t >= off) ? part[t - off] : 0;
        __syncthreads();
        part[t] += v;
        __syncthreads();
    }
    int run = part[t] - s;   // exclusive prefix of this chunk
    for (int i = lo; i < hi; i++) {
        int c = g_CNT[i];
        g_CNT[i] = run;
        g_OFF[i] = run;
        run += c;
    }
}

__global__ void scatter_kernel() {
    int e = blockIdx.x * blockDim.x + threadIdx.x;
    if (e >= EE) return;
    int src = g_src[e], dst = g_dst[e], k0 = g_K0[e];
    int pos = atomicAdd(&g_OFF[src], 1);
    float inv = g_DEG[dst];           // already 1/max(deg,1)
    float4 b = g_B[e];
    s_meta[pos] = make_int4(src, dst, k0, 0);
    s_B[pos] = make_float4(b.x * inv, b.y * inv, b.z * inv, b.w * inv);
}

// ---------------- mma / ldmatrix / stmatrix helpers ---------------------------
__device__ __forceinline__ uint32_t pack_h2(float a, float b) {
    uint32_t r;
    asm("cvt.rn.f16x2.f32 %0, %1, %2;" : "=r"(r) : "f"(b), "f"(a));
    return r;
}

__device__ __forceinline__ void mma_f16(float c[4], const uint32_t a[4],
                                        const uint32_t b[2]) {
    asm volatile(
        "mma.sync.aligned.m16n8k16.row.col.f32.f16.f16.f32 "
        "{%0,%1,%2,%3}, {%4,%5,%6,%7}, {%8,%9}, {%0,%1,%2,%3};\n"
        : "+f"(c[0]), "+f"(c[1]), "+f"(c[2]), "+f"(c[3])
        : "r"(a[0]), "r"(a[1]), "r"(a[2]), "r"(a[3]),
          "r"(b[0]), "r"(b[1]));
}

__device__ __forceinline__ void ldsm_x4(uint32_t r[4], uint32_t addr) {
    asm volatile("ldmatrix.sync.aligned.m8n8.x4.shared.b16 {%0,%1,%2,%3}, [%4];"
                 : "=r"(r[0]), "=r"(r[1]), "=r"(r[2]), "=r"(r[3]) : "r"(addr));
}

__device__ __forceinline__ void ldsm_x2t(uint32_t r[2], uint32_t addr) {
    asm volatile("ldmatrix.sync.aligned.m8n8.x2.trans.shared.b16 {%0,%1}, [%2];"
                 : "=r"(r[0]), "=r"(r[1]) : "r"(addr));
}

__device__ __forceinline__ void stsm_x4(uint32_t addr, uint32_t r0, uint32_t r1,
                                        uint32_t r2, uint32_t r3) {
    asm volatile("stmatrix.sync.aligned.m8n8.x4.shared.b16 [%0], {%1,%2,%3,%4};"
                 :: "r"(addr), "r"(r0), "r"(r1), "r"(r2), "r"(r3));
}

// ---------------- Y = X @ W[k]; stmatrix-staged coalesced Y stores -----------
template <int CIN>
__global__ void __launch_bounds__(256)
gemm_y_h(const float* __restrict__ X, const float* __restrict__ W) {
    constexpr int SW  = CIN / 2 + 4;
    constexpr int WSW = 36;
    constexpr int KS  = CIN / 16;
    constexpr int NJ  = CIN / 16;
    extern __shared__ uint32_t sh[];
    uint32_t* Xs = sh;
    uint32_t* Ws = sh + 128 * SW;
    __half*   Cs = (__half*)(Ws + 2 * CIN * WSW);

    const int tid  = threadIdx.x;
    const int lane = tid & 31;
    const int wid  = tid >> 5;
    const int rowB = (wid >> 1) * 32;
    const int colB = (wid & 1) * 32;
    const int n0   = blockIdx.x * 128;
    const int kb   = blockIdx.y * KGRP;

    for (int i = tid; i < 128 * (CIN / 4); i += 256) {
        int r  = i / (CIN / 4);
        int c4 = (i % (CIN / 4)) * 4;
        float4 v = make_float4(0.f, 0.f, 0.f, 0.f);
        if (n0 + r < NN)
            v = __ldg((const float4*)(X + (size_t)(n0 + r) * CIN + c4));
        *(uint2*)&Xs[r * SW + c4 / 2] =
            make_uint2(pack_h2(v.x, v.y), pack_h2(v.z, v.w));
    }
    float4 wreg[NJ];
    {
        const float4* Wp = (const float4*)(W + (size_t)kb * CIN * 64);
        #pragma unroll
        for (int j = 0; j < NJ; j++) wreg[j] = __ldg(Wp + tid + j * 256);
    }
    __syncthreads();

    uint32_t a[2][KS][4];
    #pragma unroll
    for (int mt = 0; mt < 2; mt++)
        #pragma unroll
        for (int ks = 0; ks < KS; ks++) {
            int m  = rowB + mt * 16 + (lane & 15);
            int kw = ks * 8 + (lane >> 4) * 4;
            uint32_t addr = (uint32_t)__cvta_generic_to_shared(&Xs[m * SW + kw]);
            ldsm_x4(a[mt][ks], addr);
        }

    #pragma unroll
    for (int j = 0; j < NJ; j++) {
        int lin = (tid + j * 256) * 4;
        int kin = lin / 64, nn = lin % 64;
        float4 v = wreg[j];
        *(uint2*)&Ws[kin * WSW + nn / 2] =
            make_uint2(pack_h2(v.x, v.y), pack_h2(v.z, v.w));
    }
    {
        const float4* Wp = (const float4*)(W + (size_t)(kb + 1) * CIN * 64);
        #pragma unroll
        for (int j = 0; j < NJ; j++) wreg[j] = __ldg(Wp + tid + j * 256);
    }
    __syncthreads();

    const int st_t  = lane >> 3;
    const int st_rr = lane & 7;

    #pragma unroll
    for (int kk = 0; kk < KGRP; kk++) {
        const int k = kb + kk;
        if (kk + 1 < KGRP) {
            uint32_t* wnext = Ws + ((kk + 1) & 1) * CIN * WSW;
            #pragma unroll
            for (int j = 0; j < NJ; j++) {
                int lin = (tid + j * 256) * 4;
                int kin = lin / 64, nn = lin % 64;
                float4 v = wreg[j];
                *(uint2*)&wnext[kin * WSW + nn / 2] =
                    make_uint2(pack_h2(v.x, v.y), pack_h2(v.z, v.w));
            }
            if (kk + 2 < KGRP) {
                const float4* Wp = (const float4*)(W + (size_t)(k + 2) * CIN * 64);
                #pragma unroll
                for (int j = 0; j < NJ; j++) wreg[j] = __ldg(Wp + tid + j * 256);
            }
        }

        float c[2][4][4];
        #pragma unroll
        for (int mt = 0; mt < 2; mt++)
            #pragma unroll
            for (int nt = 0; nt < 4; nt++)
                #pragma unroll
                for (int q = 0; q < 4; q++) c[mt][nt][q] = 0.f;

        const uint32_t* wbuf = Ws + (kk & 1) * CIN * WSW;
        #pragma unroll
        for (int nt = 0; nt < 4; nt++) {
            #pragma unroll
            for (int ks = 0; ks < KS; ks++) {
                uint32_t b[2];
                int kr = ks * 16 + (lane & 15);
                uint32_t addr = (uint32_t)__cvta_generic_to_shared(
                    &wbuf[kr * WSW + (colB + nt * 8) / 2]);
                ldsm_x2t(b, addr);
                mma_f16(c[0][nt], a[0][ks], b);
                mma_f16(c[1][nt], a[1][ks], b);
            }
        }

        #pragma unroll
        for (int mt = 0; mt < 2; mt++) {
            #pragma unroll
            for (int np = 0; np < 2; np++) {
                int row = rowB + mt * 16 + ((st_t & 1) ? 8 : 0) + st_rr;
                int col = colB + np * 16 + (st_t >> 1) * 8;
                uint32_t addr = (uint32_t)__cvta_generic_to_shared(
                    &Cs[row * CSW + col]);
                stsm_x4(addr,
                        pack_h2(c[mt][np * 2 + 0][0], c[mt][np * 2 + 0][1]),
                        pack_h2(c[mt][np * 2 + 0][2], c[mt][np * 2 + 0][3]),
                        pack_h2(c[mt][np * 2 + 1][0], c[mt][np * 2 + 1][1]),
                        pack_h2(c[mt][np * 2 + 1][2], c[mt][np * 2 + 1][3]));
            }
        }
        __syncthreads();

        #pragma unroll
        for (int j = 0; j < 4; j++) {
            int idx = tid + j * 256;
            int row = idx >> 3;
            int seg = idx & 7;
            uint4 v = *(uint4*)&Cs[row * CSW + seg * 8];
            if (n0 + row < NN)
                *(uint4*)&g_Yh[(size_t)(n0 + row) * YSTRIDE + k * 64 + seg * 8] = v;
        }
        __syncthreads();
    }
}

// ---------------- per-edge gather (sorted by src) + RED scatter --------------
__global__ void edge_kernel() {
    int t = blockIdx.x * blockDim.x + threadIdx.x;
    int e = t >> 4;
    int lane = t & 15;
    if (e >= EE) return;

    int4 md = __ldg(&s_meta[e]);     // x=src, y=dst, z=k0
    float4 b = __ldg(&s_B[e]);       // basis * 1/deg

    const uint2* base = (const uint2*)(g_Yh + (size_t)md.x * YSTRIDE + md.z * 64);
    uint2 q0 = __ldg(base + lane);
    uint2 q1 = __ldg(base + 16 + lane);
    uint2 q2 = __ldg(base + 80 + lane);
    uint2 q3 = __ldg(base + 96 + lane);

    float2 a0 = __half22float2(*(__half2*)&q0.x), a1 = __half22float2(*(__half2*)&q0.y);
    float2 b0 = __half22float2(*(__half2*)&q1.x), b1 = __half22float2(*(__half2*)&q1.y);
    float2 c0 = __half22float2(*(__half2*)&q2.x), c1 = __half22float2(*(__half2*)&q2.y);
    float2 d0 = __half22float2(*(__half2*)&q3.x), d1 = __half22float2(*(__half2*)&q3.y);

    float4 m;
    m.x = b.x * a0.x + b.y * b0.x + b.z * c0.x + b.w * d0.x;
    m.y = b.x * a0.y + b.y * b0.y + b.z * c0.y + b.w * d0.y;
    m.z = b.x * a1.x + b.y * b1.x + b.z * c1.x + b.w * d1.x;
    m.w = b.x * a1.y + b.y * b1.y + b.z * c1.y + b.w * d1.y;

    float* dptr = g_AGG + (size_t)md.y * 64 + lane * 4;
    asm volatile("red.global.add.v4.f32 [%0], {%1, %2, %3, %4};"
                 :: "l"(dptr), "f"(m.x), "f"(m.y), "f"(m.z), "f"(m.w)
                 : "memory");
}

// ---------------- finalize: 32 nodes/block ------------------------------------
template <int CIN>
__global__ void __launch_bounds__(512)
finalize_kernel(const float* __restrict__ X,
                const float* __restrict__ root,
                const float* __restrict__ bias,
                float* __restrict__ H) {
    __shared__ __align__(16) float rs[CIN * 64];
    __shared__ __align__(16) float xs[32 * CIN];
    const int tid = threadIdx.x;

    for (int i = tid; i < CIN * 16; i += 512)
        ((float4*)rs)[i] = __ldg(((const float4*)root) + i);

    const int n0 = blockIdx.x * 32;
    for (int i = tid; i < 32 * CIN / 4; i += 512) {
        int lin = i * 4;
        int r = lin / CIN, c = lin % CIN;
        int n = n0 + r;
        float4 v = make_float4(0.f, 0.f, 0.f, 0.f);
        if (n < NN) v = __ldg((const float4*)(X + (size_t)n * CIN + c));
        *(float4*)&xs[r * CIN + c] = v;
    }
    __syncthreads();

    const int o  = tid & 63;
    const float bi = __ldg(bias + o);

    #pragma unroll
    for (int p = 0; p < 4; p++) {
        int ln = p * 8 + (tid >> 6);
        int n  = n0 + ln;
        if (n >= NN) break;
        float acc = 0.f;
        #pragma unroll
        for (int i = 0; i < CIN; i++)
            acc = fmaf(xs[ln * CIN + i], rs[i * 64 + o], acc);
        size_t ai = (size_t)n * 64 + o;
        float v = g_AGG[ai] + acc + bi;
        g_AGG[ai] = 0.0f;
        H[ai] = fmaxf(v, 0.0f);
    }
}

// ---------------- final: concat(x,h1,h2) @ fw + fb, 32 nodes/block -----------
__global__ void __launch_bounds__(512)
final_kernel(const float* __restrict__ X,
             const float* __restrict__ fw,
             const float* __restrict__ fb,
             float* __restrict__ out) {
    extern __shared__ float fsm[];
    float* ws = fsm;                 // [FIN*64]
    float* xs = fsm + FIN * 64;      // [32*FIN]
    const int tid = threadIdx.x;

    for (int i = tid; i < FIN * 16; i += 512)
        ((float4*)ws)[i] = __ldg(((const float4*)fw) + i);

    const int n0 = blockIdx.x * 32;
    for (int i = tid; i < 32 * FIN / 4; i += 512) {
        int lin = i * 4;
        int r = lin / FIN, c = lin % FIN;
        int n = n0 + r;
        float4 v = make_float4(0.f, 0.f, 0.f, 0.f);
        if (n < NN) {
            if (c < 32)      v = __ldg((const float4*)(X    + (size_t)n * 32 + c));
            else if (c < 96) v = __ldg((const float4*)(g_H1 + (size_t)n * 64 + (c - 32)));
            else             v = __ldg((const float4*)(g_H2 + (size_t)n * 64 + (c - 96)));
        }
        *(float4*)&xs[r * FIN + c] = v;
    }
    __syncthreads();

    const int o = tid & 63;
    const float bi = __ldg(fb + o);

    #pragma unroll
    for (int p = 0; p < 4; p++) {
        int ln = p * 8 + (tid >> 6);
        int n  = n0 + ln;
        if (n >= NN) break;
        float acc = bi;
        #pragma unroll
        for (int i = 0; i < FIN; i++)
            acc = fmaf(xs[ln * FIN + i], ws[i * 64 + o], acc);
        out[(size_t)n * 64 + o] = acc;
    }
}

// ---------------- launch -----------------------------------------------------
extern "C" void kernel_launch(void* const* d_in, const int* in_sizes, int n_in,
                              void* d_out, int out_size) {
    const float* x     = (const float*)d_in[0];
    const int*   ei    = (const int*)d_in[1];     // int32 (jax x64 disabled)
    const float* ea    = (const float*)d_in[2];
    const float* w0    = (const float*)d_in[3];
    const float* root0 = (const float*)d_in[4];
    const float* b0    = (const float*)d_in[5];
    const float* w1    = (const float*)d_in[6];
    const float* root1 = (const float*)d_in[7];
    const float* b1    = (const float*)d_in[8];
    const float* fw    = (const float*)d_in[9];
    const float* fb    = (const float*)d_in[10];
    float*       out   = (float*)d_out;

    float *h1p, *h2p;
    cudaGetSymbolAddress((void**)&h1p, g_H1);
    cudaGetSymbolAddress((void**)&h2p, g_H2);

    const int smem0 = (128 * (C0 / 2 + 4) + 2 * C0 * 36) * 4 + 128 * CSW * 2;
    const int smem1 = (128 * (C1 / 2 + 4) + 2 * C1 * 36) * 4 + 128 * CSW * 2;
    const int smemF = (FIN * 64 + 32 * FIN) * 4;   // 61440 B
    cudaFuncSetAttribute(gemm_y_h<C0>, cudaFuncAttributeMaxDynamicSharedMemorySize, smem0);
    cudaFuncSetAttribute(gemm_y_h<C1>, cudaFuncAttributeMaxDynamicSharedMemorySize, smem1);
    cudaFuncSetAttribute(final_kernel, cudaFuncAttributeMaxDynamicSharedMemorySize, smemF);

    const int zgrid = (NN * 64 + 255) / 256;
    dim3 ggrid((NN + 127) / 128, KP / KGRP);
    const int egrid = (EE * 16 + 255) / 256;
    const int fgrid = (NN + 31) / 32;

    init_kernel<<<zgrid, 256>>>();
    prep_kernel<<<(EE + 255) / 256, 256>>>(ei, ea);
    recip_kernel<<<(NN + 255) / 256, 256>>>();
    scan_kernel<<<1, 1024>>>();
    scatter_kernel<<<(EE + 255) / 256, 256>>>();

    // ---- layer 0 (cin = 32) ----
    gemm_y_h<C0><<<ggrid, 256, smem0>>>(x, w0);
    edge_kernel<<<egrid, 256>>>();
    finalize_kernel<C0><<<fgrid, 512>>>(x, root0, b0, h1p);

    // ---- layer 1 (cin = 64) ----
    gemm_y_h<C1><<<ggrid, 256, smem1>>>(h1p, w1);
    edge_kernel<<<egrid, 256>>>();
    finalize_kernel<C1><<<fgrid, 512>>>(h1p, root1, b1, h2p);

    // ---- final fused concat-GEMM ----
    final_kernel<<<fgrid, 512, smemF>>>(x, fw, fb, out);
}

// round 11
// speedup vs baseline: 1.0814x; 1.0814x over previous
#include <cuda_runtime.h>
#include <cuda_fp16.h>
#include <math.h>
#include <stdint.h>

#define NN 50000
#define EE 800000
#define C0 32
#define C1 64
#define KP 25
#define KGRP 5
#define FIN 160
#define YSTRIDE (KP * 64)   // 1600
#define CSW 72              // C-staging stride in halfs (144 B)

// ---------------- scratch -----------------------------------------------------
__device__ __align__(16) __half g_Yh[(size_t)NN * YSTRIDE];  // 160 MB fp16
__device__ __align__(16) float  g_H1[(size_t)NN * 64];
__device__ __align__(16) float  g_H2[(size_t)NN * 64];
__device__ __align__(16) float  g_AGG[(size_t)NN * 64];
__device__ __align__(16) float  g_DEG[NN];                   // 1/max(deg,1) after recip
__device__ __align__(16) float4 g_B[EE];                     // basis (pre-scaled by 1/deg)
__device__ int    g_K0[EE];
__device__ int    g_src[EE];
__device__ int    g_dst[EE];

// ---------------- init / prep / recip / scale --------------------------------
__global__ void init_kernel() {
    int i = blockIdx.x * blockDim.x + threadIdx.x;
    if (i < NN * 64) g_AGG[i] = 0.0f;
    if (i < NN)      g_DEG[i] = 0.0f;
}

__global__ void prep_kernel(const int* __restrict__ ei,
                            const float* __restrict__ ea) {
    int e = blockIdx.x * blockDim.x + threadIdx.x;
    if (e >= EE) return;
    int dst = ei[EE + e];
    g_src[e] = ei[e];
    g_dst[e] = dst;
    atomicAdd(&g_DEG[dst], 1.0f);
    float v0 = ea[2 * e + 0] * 4.0f;
    float v1 = ea[2 * e + 1] * 4.0f;
    float b0f = floorf(v0), b1f = floorf(v1);
    float f0 = v0 - b0f, f1 = v1 - b1f;
    int i0 = min((int)b0f, 3);
    int i1 = min((int)b1f, 3);
    g_K0[e] = i0 + 5 * i1;
    g_B[e] = make_float4((1.f - f0) * (1.f - f1),
                         f0 * (1.f - f1),
                         (1.f - f0) * f1,
                         f0 * f1);
}

__global__ void recip_kernel() {
    int i = blockIdx.x * blockDim.x + threadIdx.x;
    if (i < NN) g_DEG[i] = 1.0f / fmaxf(g_DEG[i], 1.0f);
}

// fold 1/deg(dst) into the basis weights once (removes DEG read from edge pass)
__global__ void scale_kernel() {
    int e = blockIdx.x * blockDim.x + threadIdx.x;
    if (e >= EE) return;
    float inv = g_DEG[g_dst[e]];
    float4 b = g_B[e];
    g_B[e] = make_float4(b.x * inv, b.y * inv, b.z * inv, b.w * inv);
}

// ---------------- mma / ldmatrix / stmatrix helpers ---------------------------
__device__ __forceinline__ uint32_t pack_h2(float a, float b) {
    uint32_t r;
    asm("cvt.rn.f16x2.f32 %0, %1, %2;" : "=r"(r) : "f"(b), "f"(a));
    return r;
}

__device__ __forceinline__ void mma_f16(float c[4], const uint32_t a[4],
                                        const uint32_t b[2]) {
    asm volatile(
        "mma.sync.aligned.m16n8k16.row.col.f32.f16.f16.f32 "
        "{%0,%1,%2,%3}, {%4,%5,%6,%7}, {%8,%9}, {%0,%1,%2,%3};\n"
        : "+f"(c[0]), "+f"(c[1]), "+f"(c[2]), "+f"(c[3])
        : "r"(a[0]), "r"(a[1]), "r"(a[2]), "r"(a[3]),
          "r"(b[0]), "r"(b[1]));
}

__device__ __forceinline__ void ldsm_x4(uint32_t r[4], uint32_t addr) {
    asm volatile("ldmatrix.sync.aligned.m8n8.x4.shared.b16 {%0,%1,%2,%3}, [%4];"
                 : "=r"(r[0]), "=r"(r[1]), "=r"(r[2]), "=r"(r[3]) : "r"(addr));
}

__device__ __forceinline__ void ldsm_x2t(uint32_t r[2], uint32_t addr) {
    asm volatile("ldmatrix.sync.aligned.m8n8.x2.trans.shared.b16 {%0,%1}, [%2];"
                 : "=r"(r[0]), "=r"(r[1]) : "r"(addr));
}

__device__ __forceinline__ void stsm_x4(uint32_t addr, uint32_t r0, uint32_t r1,
                                        uint32_t r2, uint32_t r3) {
    asm volatile("stmatrix.sync.aligned.m8n8.x4.shared.b16 [%0], {%1,%2,%3,%4};"
                 :: "r"(addr), "r"(r0), "r"(r1), "r"(r2), "r"(r3));
}

// ---------------- Y = X @ W[k]; stmatrix-staged coalesced Y stores -----------
template <int CIN>
__global__ void __launch_bounds__(256)
gemm_y_h(const float* __restrict__ X, const float* __restrict__ W) {
    constexpr int SW  = CIN / 2 + 4;
    constexpr int WSW = 36;
    constexpr int KS  = CIN / 16;
    constexpr int NJ  = CIN / 16;
    extern __shared__ uint32_t sh[];
    uint32_t* Xs = sh;
    uint32_t* Ws = sh + 128 * SW;
    __half*   Cs = (__half*)(Ws + 2 * CIN * WSW);

    const int tid  = threadIdx.x;
    const int lane = tid & 31;
    const int wid  = tid >> 5;
    const int rowB = (wid >> 1) * 32;
    const int colB = (wid & 1) * 32;
    const int n0   = blockIdx.x * 128;
    const int kb   = blockIdx.y * KGRP;

    for (int i = tid; i < 128 * (CIN / 4); i += 256) {
        int r  = i / (CIN / 4);
        int c4 = (i % (CIN / 4)) * 4;
        float4 v = make_float4(0.f, 0.f, 0.f, 0.f);
        if (n0 + r < NN)
            v = __ldg((const float4*)(X + (size_t)(n0 + r) * CIN + c4));
        *(uint2*)&Xs[r * SW + c4 / 2] =
            make_uint2(pack_h2(v.x, v.y), pack_h2(v.z, v.w));
    }
    float4 wreg[NJ];
    {
        const float4* Wp = (const float4*)(W + (size_t)kb * CIN * 64);
        #pragma unroll
        for (int j = 0; j < NJ; j++) wreg[j] = __ldg(Wp + tid + j * 256);
    }
    __syncthreads();

    uint32_t a[2][KS][4];
    #pragma unroll
    for (int mt = 0; mt < 2; mt++)
        #pragma unroll
        for (int ks = 0; ks < KS; ks++) {
            int m  = rowB + mt * 16 + (lane & 15);
            int kw = ks * 8 + (lane >> 4) * 4;
            uint32_t addr = (uint32_t)__cvta_generic_to_shared(&Xs[m * SW + kw]);
            ldsm_x4(a[mt][ks], addr);
        }

    #pragma unroll
    for (int j = 0; j < NJ; j++) {
        int lin = (tid + j * 256) * 4;
        int kin = lin / 64, nn = lin % 64;
        float4 v = wreg[j];
        *(uint2*)&Ws[kin * WSW + nn / 2] =
            make_uint2(pack_h2(v.x, v.y), pack_h2(v.z, v.w));
    }
    {
        const float4* Wp = (const float4*)(W + (size_t)(kb + 1) * CIN * 64);
        #pragma unroll
        for (int j = 0; j < NJ; j++) wreg[j] = __ldg(Wp + tid + j * 256);
    }
    __syncthreads();

    const int st_t  = lane >> 3;
    const int st_rr = lane & 7;

    #pragma unroll
    for (int kk = 0; kk < KGRP; kk++) {
        const int k = kb + kk;
        if (kk + 1 < KGRP) {
            uint32_t* wnext = Ws + ((kk + 1) & 1) * CIN * WSW;
            #pragma unroll
            for (int j = 0; j < NJ; j++) {
                int lin = (tid + j * 256) * 4;
                int kin = lin / 64, nn = lin % 64;
                float4 v = wreg[j];
                *(uint2*)&wnext[kin * WSW + nn / 2] =
                    make_uint2(pack_h2(v.x, v.y), pack_h2(v.z, v.w));
            }
            if (kk + 2 < KGRP) {
                const float4* Wp = (const float4*)(W + (size_t)(k + 2) * CIN * 64);
                #pragma unroll
                for (int j = 0; j < NJ; j++) wreg[j] = __ldg(Wp + tid + j * 256);
            }
        }

        float c[2][4][4];
        #pragma unroll
        for (int mt = 0; mt < 2; mt++)
            #pragma unroll
            for (int nt = 0; nt < 4; nt++)
                #pragma unroll
                for (int q = 0; q < 4; q++) c[mt][nt][q] = 0.f;

        const uint32_t* wbuf = Ws + (kk & 1) * CIN * WSW;
        #pragma unroll
        for (int nt = 0; nt < 4; nt++) {
            #pragma unroll
            for (int ks = 0; ks < KS; ks++) {
                uint32_t b[2];
                int kr = ks * 16 + (lane & 15);
                uint32_t addr = (uint32_t)__cvta_generic_to_shared(
                    &wbuf[kr * WSW + (colB + nt * 8) / 2]);
                ldsm_x2t(b, addr);
                mma_f16(c[0][nt], a[0][ks], b);
                mma_f16(c[1][nt], a[1][ks], b);
            }
        }

        #pragma unroll
        for (int mt = 0; mt < 2; mt++) {
            #pragma unroll
            for (int np = 0; np < 2; np++) {
                int row = rowB + mt * 16 + ((st_t & 1) ? 8 : 0) + st_rr;
                int col = colB + np * 16 + (st_t >> 1) * 8;
                uint32_t addr = (uint32_t)__cvta_generic_to_shared(
                    &Cs[row * CSW + col]);
                stsm_x4(addr,
                        pack_h2(c[mt][np * 2 + 0][0], c[mt][np * 2 + 0][1]),
                        pack_h2(c[mt][np * 2 + 0][2], c[mt][np * 2 + 0][3]),
                        pack_h2(c[mt][np * 2 + 1][0], c[mt][np * 2 + 1][1]),
                        pack_h2(c[mt][np * 2 + 1][2], c[mt][np * 2 + 1][3]));
            }
        }
        __syncthreads();

        #pragma unroll
        for (int j = 0; j < 4; j++) {
            int idx = tid + j * 256;
            int row = idx >> 3;
            int seg = idx & 7;
            uint4 v = *(uint4*)&Cs[row * CSW + seg * 8];
            if (n0 + row < NN)
                *(uint4*)&g_Yh[(size_t)(n0 + row) * YSTRIDE + k * 64 + seg * 8] = v;
        }
        __syncthreads();
    }
}

// ---------------- per-edge gather (fp16 Y) + combine + vector-RED scatter ----
__global__ void edge_kernel() {
    int t = blockIdx.x * blockDim.x + threadIdx.x;
    int e = t >> 4;
    int lane = t & 15;
    if (e >= EE) return;

    int src = g_src[e];
    int dst = g_dst[e];
    int k0  = g_K0[e];
    float4 b = g_B[e];   // pre-scaled by 1/deg(dst)

    const uint2* base = (const uint2*)(g_Yh + (size_t)src * YSTRIDE + k0 * 64);
    uint2 q0 = __ldg(base + lane);        // row k0
    uint2 q1 = __ldg(base + 16 + lane);   // row k0+1
    uint2 q2 = __ldg(base + 80 + lane);   // row k0+5
    uint2 q3 = __ldg(base + 96 + lane);   // row k0+6

    float2 a0 = __half22float2(*(__half2*)&q0.x), a1 = __half22float2(*(__half2*)&q0.y);
    float2 b0 = __half22float2(*(__half2*)&q1.x), b1 = __half22float2(*(__half2*)&q1.y);
    float2 c0 = __half22float2(*(__half2*)&q2.x), c1 = __half22float2(*(__half2*)&q2.y);
    float2 d0 = __half22float2(*(__half2*)&q3.x), d1 = __half22float2(*(__half2*)&q3.y);

    float4 m;
    m.x = b.x * a0.x + b.y * b0.x + b.z * c0.x + b.w * d0.x;
    m.y = b.x * a0.y + b.y * b0.y + b.z * c0.y + b.w * d0.y;
    m.z = b.x * a1.x + b.y * b1.x + b.z * c1.x + b.w * d1.x;
    m.w = b.x * a1.y + b.y * b1.y + b.z * c1.y + b.w * d1.y;

    float* dptr = g_AGG + (size_t)dst * 64 + lane * 4;
    asm volatile("red.global.add.v4.f32 [%0], {%1, %2, %3, %4};"
                 :: "l"(dptr), "f"(m.x), "f"(m.y), "f"(m.z), "f"(m.w)
                 : "memory");
}

// ---------------- finalize: 32 nodes/block ------------------------------------
template <int CIN>
__global__ void __launch_bounds__(512)
finalize_kernel(const float* __restrict__ X,
                const float* __restrict__ root,
                const float* __restrict__ bias,
                float* __restrict__ H) {
    __shared__ __align__(16) float rs[CIN * 64];
    __shared__ __align__(16) float xs[32 * CIN];
    const int tid = threadIdx.x;

    for (int i = tid; i < CIN * 16; i += 512)
        ((float4*)rs)[i] = __ldg(((const float4*)root) + i);

    const int n0 = blockIdx.x * 32;
    for (int i = tid; i < 32 * CIN / 4; i += 512) {
        int lin = i * 4;
        int r = lin / CIN, c = lin % CIN;
        int n = n0 + r;
        float4 v = make_float4(0.f, 0.f, 0.f, 0.f);
        if (n < NN) v = __ldg((const float4*)(X + (size_t)n * CIN + c));
        *(float4*)&xs[r * CIN + c] = v;
    }
    __syncthreads();

    const int o  = tid & 63;
    const float bi = __ldg(bias + o);

    #pragma unroll
    for (int p = 0; p < 4; p++) {
        int ln = p * 8 + (tid >> 6);
        int n  = n0 + ln;
        if (n >= NN) break;
        float acc = 0.f;
        #pragma unroll
        for (int i = 0; i < CIN; i++)
            acc = fmaf(xs[ln * CIN + i], rs[i * 64 + o], acc);
        size_t ai = (size_t)n * 64 + o;
        float v = g_AGG[ai] + acc + bi;
        g_AGG[ai] = 0.0f;
        H[ai] = fmaxf(v, 0.0f);
    }
}

// ---------------- final: concat(x,h1,h2) @ fw + fb, 32 nodes/block -----------
__global__ void __launch_bounds__(512)
final_kernel(const float* __restrict__ X,
             const float* __restrict__ fw,
             const float* __restrict__ fb,
             float* __restrict__ out) {
    extern __shared__ float fsm[];
    float* ws = fsm;                 // [FIN*64]
    float* xs = fsm + FIN * 64;      // [32*FIN]
    const int tid = threadIdx.x;

    for (int i = tid; i < FIN * 16; i += 512)
        ((float4*)ws)[i] = __ldg(((const float4*)fw) + i);

    const int n0 = blockIdx.x * 32;
    for (int i = tid; i < 32 * FIN / 4; i += 512) {
        int lin = i * 4;
        int r = lin / FIN, c = lin % FIN;
        int n = n0 + r;
        float4 v = make_float4(0.f, 0.f, 0.f, 0.f);
        if (n < NN) {
            if (c < 32)      v = __ldg((const float4*)(X    + (size_t)n * 32 + c));
            else if (c < 96) v = __ldg((const float4*)(g_H1 + (size_t)n * 64 + (c - 32)));
            else             v = __ldg((const float4*)(g_H2 + (size_t)n * 64 + (c - 96)));
        }
        *(float4*)&xs[r * FIN + c] = v;
    }
    __syncthreads();

    const int o = tid & 63;
    const float bi = __ldg(fb + o);

    #pragma unroll
    for (int p = 0; p < 4; p++) {
        int ln = p * 8 + (tid >> 6);
        int n  = n0 + ln;
        if (n >= NN) break;
        float acc = bi;
        #pragma unroll
        for (int i = 0; i < FIN; i++)
            acc = fmaf(xs[ln * FIN + i], ws[i * 64 + o], acc);
        out[(size_t)n * 64 + o] = acc;
    }
}

// ---------------- launch -----------------------------------------------------
extern "C" void kernel_launch(void* const* d_in, const int* in_sizes, int n_in,
                              void* d_out, int out_size) {
    const float* x     = (const float*)d_in[0];
    const int*   ei    = (const int*)d_in[1];     // int32 (jax x64 disabled)
    const float* ea    = (const float*)d_in[2];
    const float* w0    = (const float*)d_in[3];
    const float* root0 = (const float*)d_in[4];
    const float* b0    = (const float*)d_in[5];
    const float* w1    = (const float*)d_in[6];
    const float* root1 = (const float*)d_in[7];
    const float* b1    = (const float*)d_in[8];
    const float* fw    = (const float*)d_in[9];
    const float* fb    = (const float*)d_in[10];
    float*       out   = (float*)d_out;

    float *h1p, *h2p;
    cudaGetSymbolAddress((void**)&h1p, g_H1);
    cudaGetSymbolAddress((void**)&h2p, g_H2);

    const int smem0 = (128 * (C0 / 2 + 4) + 2 * C0 * 36) * 4 + 128 * CSW * 2;
    const int smem1 = (128 * (C1 / 2 + 4) + 2 * C1 * 36) * 4 + 128 * CSW * 2;
    const int smemF = (FIN * 64 + 32 * FIN) * 4;   // 61440 B
    cudaFuncSetAttribute(gemm_y_h<C0>, cudaFuncAttributeMaxDynamicSharedMemorySize, smem0);
    cudaFuncSetAttribute(gemm_y_h<C1>, cudaFuncAttributeMaxDynamicSharedMemorySize, smem1);
    cudaFuncSetAttribute(final_kernel, cudaFuncAttributeMaxDynamicSharedMemorySize, smemF);

    const int zgrid = (NN * 64 + 255) / 256;
    dim3 ggrid((NN + 127) / 128, KP / KGRP);
    const int egrid = (EE * 16 + 255) / 256;
    const int fgrid = (NN + 31) / 32;

    init_kernel<<<zgrid, 256>>>();
    prep_kernel<<<(EE + 255) / 256, 256>>>(ei, ea);
    recip_kernel<<<(NN + 255) / 256, 256>>>();
    scale_kernel<<<(EE + 255) / 256, 256>>>();

    // ---- layer 0 (cin = 32) ----
    gemm_y_h<C0><<<ggrid, 256, smem0>>>(x, w0);
    edge_kernel<<<egrid, 256>>>();
    finalize_kernel<C0><<<fgrid, 512>>>(x, root0, b0, h1p);

    // ---- layer 1 (cin = 64) ----
    gemm_y_h<C1><<<ggrid, 256, smem1>>>(h1p, w1);
    edge_kernel<<<egrid, 256>>>();
    finalize_kernel<C1><<<fgrid, 512>>>(h1p, root1, b1, h2p);

    // ---- final fused concat-GEMM ----
    final_kernel<<<fgrid, 512, smemF>>>(x, fw, fb, out);
}

// round 13
// speedup vs baseline: 1.5725x; 1.4542x over previous
#include <cuda_runtime.h>
#include <cuda_fp16.h>
#include <math.h>
#include <stdint.h>

#define NN 50000
#define EE 800000
#define C0 32
#define C1 64
#define KP 25
#define KGRP 5
#define FIN 160
#define YSTRIDE (KP * 64)   // 1600
#define CSW 72              // C-staging stride in halfs (144 B)

// ---------------- scratch -----------------------------------------------------
__device__ __align__(16) __half g_Yh[(size_t)NN * YSTRIDE];  // 160 MB fp16
__device__ __align__(16) float  g_H1[(size_t)NN * 64];
__device__ __align__(16) float  g_H2[(size_t)NN * 64];
__device__ __align__(16) float  g_AGG[(size_t)NN * 64];
__device__ __align__(16) float  g_DEG[NN];                   // 1/max(deg,1) after recip
__device__ __align__(16) float4 g_B[EE];                     // basis (pre-scaled by 1/deg)
__device__ int    g_K0[EE];
__device__ int    g_src[EE];
__device__ int    g_dst[EE];

// ---------------- init / prep / recip / scale --------------------------------
__global__ void init_kernel() {
    int i = blockIdx.x * blockDim.x + threadIdx.x;
    if (i < NN * 64) g_AGG[i] = 0.0f;
    if (i < NN)      g_DEG[i] = 0.0f;
}

__global__ void prep_kernel(const int* __restrict__ ei,
                            const float* __restrict__ ea) {
    int e = blockIdx.x * blockDim.x + threadIdx.x;
    if (e >= EE) return;
    int dst = ei[EE + e];
    g_src[e] = ei[e];
    g_dst[e] = dst;
    atomicAdd(&g_DEG[dst], 1.0f);
    float v0 = ea[2 * e + 0] * 4.0f;
    float v1 = ea[2 * e + 1] * 4.0f;
    float b0f = floorf(v0), b1f = floorf(v1);
    float f0 = v0 - b0f, f1 = v1 - b1f;
    int i0 = min((int)b0f, 3);
    int i1 = min((int)b1f, 3);
    g_K0[e] = i0 + 5 * i1;
    g_B[e] = make_float4((1.f - f0) * (1.f - f1),
                         f0 * (1.f - f1),
                         (1.f - f0) * f1,
                         f0 * f1);
}

__global__ void recip_kernel() {
    int i = blockIdx.x * blockDim.x + threadIdx.x;
    if (i < NN) g_DEG[i] = 1.0f / fmaxf(g_DEG[i], 1.0f);
}

// fold 1/deg(dst) into the basis weights once per launch (prep rewrites g_B
// each replay, so this stays idempotent across graph replays).
__global__ void scale_kernel() {
    int e = blockIdx.x * blockDim.x + threadIdx.x;
    if (e >= EE) return;
    float inv = g_DEG[g_dst[e]];
    float4 b = g_B[e];
    g_B[e] = make_float4(b.x * inv, b.y * inv, b.z * inv, b.w * inv);
}

// ---------------- mma / ldmatrix / stmatrix helpers ---------------------------
__device__ __forceinline__ uint32_t pack_h2(float a, float b) {
    uint32_t r;
    asm("cvt.rn.f16x2.f32 %0, %1, %2;" : "=r"(r) : "f"(b), "f"(a));
    return r;
}

__device__ __forceinline__ void mma_f16(float c[4], const uint32_t a[4],
                                        const uint32_t b[2]) {
    asm volatile(
        "mma.sync.aligned.m16n8k16.row.col.f32.f16.f16.f32 "
        "{%0,%1,%2,%3}, {%4,%5,%6,%7}, {%8,%9}, {%0,%1,%2,%3};\n"
        : "+f"(c[0]), "+f"(c[1]), "+f"(c[2]), "+f"(c[3])
        : "r"(a[0]), "r"(a[1]), "r"(a[2]), "r"(a[3]),
          "r"(b[0]), "r"(b[1]));
}

__device__ __forceinline__ void ldsm_x4(uint32_t r[4], uint32_t addr) {
    asm volatile("ldmatrix.sync.aligned.m8n8.x4.shared.b16 {%0,%1,%2,%3}, [%4];"
                 : "=r"(r[0]), "=r"(r[1]), "=r"(r[2]), "=r"(r[3]) : "r"(addr));
}

__device__ __forceinline__ void ldsm_x2t(uint32_t r[2], uint32_t addr) {
    asm volatile("ldmatrix.sync.aligned.m8n8.x2.trans.shared.b16 {%0,%1}, [%2];"
                 : "=r"(r[0]), "=r"(r[1]) : "r"(addr));
}

__device__ __forceinline__ void stsm_x4(uint32_t addr, uint32_t r0, uint32_t r1,
                                        uint32_t r2, uint32_t r3) {
    asm volatile("stmatrix.sync.aligned.m8n8.x4.shared.b16 [%0], {%1,%2,%3,%4};"
                 :: "r"(addr), "r"(r0), "r"(r1), "r"(r2), "r"(r3));
}

// ---------------- Y = X @ W[k]; stmatrix-staged coalesced Y stores -----------
template <int CIN>
__global__ void __launch_bounds__(256)
gemm_y_h(const float* __restrict__ X, const float* __restrict__ W) {
    constexpr int SW  = CIN / 2 + 4;
    constexpr int WSW = 36;
    constexpr int KS  = CIN / 16;
    constexpr int NJ  = CIN / 16;
    extern __shared__ uint32_t sh[];
    uint32_t* Xs = sh;
    uint32_t* Ws = sh + 128 * SW;
    __half*   Cs = (__half*)(Ws + 2 * CIN * WSW);

    const int tid  = threadIdx.x;
    const int lane = tid & 31;
    const int wid  = tid >> 5;
    const int rowB = (wid >> 1) * 32;
    const int colB = (wid & 1) * 32;
    const int n0   = blockIdx.x * 128;
    const int kb   = blockIdx.y * KGRP;

    for (int i = tid; i < 128 * (CIN / 4); i += 256) {
        int r  = i / (CIN / 4);
        int c4 = (i % (CIN / 4)) * 4;
        float4 v = make_float4(0.f, 0.f, 0.f, 0.f);
        if (n0 + r < NN)
            v = __ldg((const float4*)(X + (size_t)(n0 + r) * CIN + c4));
        *(uint2*)&Xs[r * SW + c4 / 2] =
            make_uint2(pack_h2(v.x, v.y), pack_h2(v.z, v.w));
    }
    float4 wreg[NJ];
    {
        const float4* Wp = (const float4*)(W + (size_t)kb * CIN * 64);
        #pragma unroll
        for (int j = 0; j < NJ; j++) wreg[j] = __ldg(Wp + tid + j * 256);
    }
    __syncthreads();

    uint32_t a[2][KS][4];
    #pragma unroll
    for (int mt = 0; mt < 2; mt++)
        #pragma unroll
        for (int ks = 0; ks < KS; ks++) {
            int m  = rowB + mt * 16 + (lane & 15);
            int kw = ks * 8 + (lane >> 4) * 4;
            uint32_t addr = (uint32_t)__cvta_generic_to_shared(&Xs[m * SW + kw]);
            ldsm_x4(a[mt][ks], addr);
        }

    #pragma unroll
    for (int j = 0; j < NJ; j++) {
        int lin = (tid + j * 256) * 4;
        int kin = lin / 64, nn = lin % 64;
        float4 v = wreg[j];
        *(uint2*)&Ws[kin * WSW + nn / 2] =
            make_uint2(pack_h2(v.x, v.y), pack_h2(v.z, v.w));
    }
    {
        const float4* Wp = (const float4*)(W + (size_t)(kb + 1) * CIN * 64);
        #pragma unroll
        for (int j = 0; j < NJ; j++) wreg[j] = __ldg(Wp + tid + j * 256);
    }
    __syncthreads();

    const int st_t  = lane >> 3;
    const int st_rr = lane & 7;

    #pragma unroll
    for (int kk = 0; kk < KGRP; kk++) {
        const int k = kb + kk;
        if (kk + 1 < KGRP) {
            uint32_t* wnext = Ws + ((kk + 1) & 1) * CIN * WSW;
            #pragma unroll
            for (int j = 0; j < NJ; j++) {
                int lin = (tid + j * 256) * 4;
                int kin = lin / 64, nn = lin % 64;
                float4 v = wreg[j];
                *(uint2*)&wnext[kin * WSW + nn / 2] =
                    make_uint2(pack_h2(v.x, v.y), pack_h2(v.z, v.w));
            }
            if (kk + 2 < KGRP) {
                const float4* Wp = (const float4*)(W + (size_t)(k + 2) * CIN * 64);
                #pragma unroll
                for (int j = 0; j < NJ; j++) wreg[j] = __ldg(Wp + tid + j * 256);
            }
        }

        float c[2][4][4];
        #pragma unroll
        for (int mt = 0; mt < 2; mt++)
            #pragma unroll
            for (int nt = 0; nt < 4; nt++)
                #pragma unroll
                for (int q = 0; q < 4; q++) c[mt][nt][q] = 0.f;

        const uint32_t* wbuf = Ws + (kk & 1) * CIN * WSW;
        #pragma unroll
        for (int nt = 0; nt < 4; nt++) {
            #pragma unroll
            for (int ks = 0; ks < KS; ks++) {
                uint32_t b[2];
                int kr = ks * 16 + (lane & 15);
                uint32_t addr = (uint32_t)__cvta_generic_to_shared(
                    &wbuf[kr * WSW + (colB + nt * 8) / 2]);
                ldsm_x2t(b, addr);
                mma_f16(c[0][nt], a[0][ks], b);
                mma_f16(c[1][nt], a[1][ks], b);
            }
        }

        #pragma unroll
        for (int mt = 0; mt < 2; mt++) {
            #pragma unroll
            for (int np = 0; np < 2; np++) {
                int row = rowB + mt * 16 + ((st_t & 1) ? 8 : 0) + st_rr;
                int col = colB + np * 16 + (st_t >> 1) * 8;
                uint32_t addr = (uint32_t)__cvta_generic_to_shared(
                    &Cs[row * CSW + col]);
                stsm_x4(addr,
                        pack_h2(c[mt][np * 2 + 0][0], c[mt][np * 2 + 0][1]),
                        pack_h2(c[mt][np * 2 + 0][2], c[mt][np * 2 + 0][3]),
                        pack_h2(c[mt][np * 2 + 1][0], c[mt][np * 2 + 1][1]),
                        pack_h2(c[mt][np * 2 + 1][2], c[mt][np * 2 + 1][3]));
            }
        }
        __syncthreads();

        #pragma unroll
        for (int j = 0; j < 4; j++) {
            int idx = tid + j * 256;
            int row = idx >> 3;
            int seg = idx & 7;
            uint4 v = *(uint4*)&Cs[row * CSW + seg * 8];
            if (n0 + row < NN)
                *(uint4*)&g_Yh[(size_t)(n0 + row) * YSTRIDE + k * 64 + seg * 8] = v;
        }
        __syncthreads();
    }
}

// ---------------- per-edge gather (fp16 Y) + combine + vector-RED scatter ----
__global__ void edge_kernel() {
    int t = blockIdx.x * blockDim.x + threadIdx.x;
    int e = t >> 4;
    int lane = t & 15;
    if (e >= EE) return;

    int src = g_src[e];
    int dst = g_dst[e];
    int k0  = g_K0[e];
    float4 b = g_B[e];   // pre-scaled by 1/deg(dst)

    const uint2* base = (const uint2*)(g_Yh + (size_t)src * YSTRIDE + k0 * 64);
    uint2 q0 = __ldg(base + lane);        // row k0
    uint2 q1 = __ldg(base + 16 + lane);   // row k0+1
    uint2 q2 = __ldg(base + 80 + lane);   // row k0+5
    uint2 q3 = __ldg(base + 96 + lane);   // row k0+6

    float2 a0 = __half22float2(*(__half2*)&q0.x), a1 = __half22float2(*(__half2*)&q0.y);
    float2 b0 = __half22float2(*(__half2*)&q1.x), b1 = __half22float2(*(__half2*)&q1.y);
    float2 c0 = __half22float2(*(__half2*)&q2.x), c1 = __half22float2(*(__half2*)&q2.y);
    float2 d0 = __half22float2(*(__half2*)&q3.x), d1 = __half22float2(*(__half2*)&q3.y);

    float4 m;
    m.x = b.x * a0.x + b.y * b0.x + b.z * c0.x + b.w * d0.x;
    m.y = b.x * a0.y + b.y * b0.y + b.z * c0.y + b.w * d0.y;
    m.z = b.x * a1.x + b.y * b1.x + b.z * c1.x + b.w * d1.x;
    m.w = b.x * a1.y + b.y * b1.y + b.z * c1.y + b.w * d1.y;

    float* dptr = g_AGG + (size_t)dst * 64 + lane * 4;
    asm volatile("red.global.add.v4.f32 [%0], {%1, %2, %3, %4};"
                 :: "l"(dptr), "f"(m.x), "f"(m.y), "f"(m.z), "f"(m.w)
                 : "memory");
}

// ---------------- finalize: 8 nodes/block (round-9 configuration) ------------
template <int CIN>
__global__ void finalize_kernel(const float* __restrict__ X,
                                const float* __restrict__ root,
                                const float* __restrict__ bias,
                                float* __restrict__ H) {
    __shared__ __align__(16) float rs[CIN * 64];
    __shared__ __align__(16) float xs[8][CIN];
    const int tid = threadIdx.x;

    for (int i = tid; i < CIN * 16; i += 512)
        ((float4*)rs)[i] = __ldg(((const float4*)root) + i);

    const int n0 = blockIdx.x * 8;
    for (int i = tid; i < 8 * CIN / 4; i += 512) {
        int lin = i * 4;
        int r = lin / CIN, c = lin % CIN;
        int n = n0 + r;
        float4 v = make_float4(0.f, 0.f, 0.f, 0.f);
        if (n < NN) v = __ldg((const float4*)(X + (size_t)n * CIN + c));
        *(float4*)&xs[r][c] = v;
    }
    __syncthreads();

    const int ln = tid >> 6;
    const int o  = tid & 63;
    const int n  = n0 + ln;
    if (n >= NN) return;

    float acc = 0.f;
    #pragma unroll
    for (int i = 0; i < CIN; i++)
        acc = fmaf(xs[ln][i], rs[i * 64 + o], acc);

    size_t ai = (size_t)n * 64 + o;
    float v = g_AGG[ai] + acc + __ldg(bias + o);
    g_AGG[ai] = 0.0f;
    H[ai] = fmaxf(v, 0.0f);
}

// ---------------- final: concat(x,h1,h2) @ fw + fb (round-9 configuration) ---
__global__ void final_kernel(const float* __restrict__ X,
                             const float* __restrict__ fw,
                             const float* __restrict__ fb,
                             float* __restrict__ out) {
    __shared__ __align__(16) float ws[FIN * 64];
    __shared__ __align__(16) float xs[8][FIN];
    const int tid = threadIdx.x;

    for (int i = tid; i < FIN * 16; i += 512)
        ((float4*)ws)[i] = __ldg(((const float4*)fw) + i);

    const int n0 = blockIdx.x * 8;
    for (int i = tid; i < 8 * FIN / 4; i += 512) {
        int lin = i * 4;
        int r = lin / FIN, c = lin % FIN;
        int n = n0 + r;
        float4 v = make_float4(0.f, 0.f, 0.f, 0.f);
        if (n < NN) {
            if (c < 32)      v = __ldg((const float4*)(X    + (size_t)n * 32 + c));
            else if (c < 96) v = __ldg((const float4*)(g_H1 + (size_t)n * 64 + (c - 32)));
            else             v = __ldg((const float4*)(g_H2 + (size_t)n * 64 + (c - 96)));
        }
        *(float4*)&xs[r][c] = v;
    }
    __syncthreads();

    const int ln = tid >> 6;
    const int o  = tid & 63;
    const int n  = n0 + ln;
    if (n >= NN) return;

    float acc = __ldg(fb + o);
    #pragma unroll
    for (int i = 0; i < FIN; i++)
        acc = fmaf(xs[ln][i], ws[i * 64 + o], acc);
    out[(size_t)n * 64 + o] = acc;
}

// ---------------- launch -----------------------------------------------------
extern "C" void kernel_launch(void* const* d_in, const int* in_sizes, int n_in,
                              void* d_out, int out_size) {
    const float* x     = (const float*)d_in[0];
    const int*   ei    = (const int*)d_in[1];     // int32 (jax x64 disabled)
    const float* ea    = (const float*)d_in[2];
    const float* w0    = (const float*)d_in[3];
    const float* root0 = (const float*)d_in[4];
    const float* b0    = (const float*)d_in[5];
    const float* w1    = (const float*)d_in[6];
    const float* root1 = (const float*)d_in[7];
    const float* b1    = (const float*)d_in[8];
    const float* fw    = (const float*)d_in[9];
    const float* fb    = (const float*)d_in[10];
    float*       out   = (float*)d_out;

    float *h1p, *h2p;
    cudaGetSymbolAddress((void**)&h1p, g_H1);
    cudaGetSymbolAddress((void**)&h2p, g_H2);

    const int smem0 = (128 * (C0 / 2 + 4) + 2 * C0 * 36) * 4 + 128 * CSW * 2;
    const int smem1 = (128 * (C1 / 2 + 4) + 2 * C1 * 36) * 4 + 128 * CSW * 2;
    cudaFuncSetAttribute(gemm_y_h<C0>, cudaFuncAttributeMaxDynamicSharedMemorySize, smem0);
    cudaFuncSetAttribute(gemm_y_h<C1>, cudaFuncAttributeMaxDynamicSharedMemorySize, smem1);

    const int zgrid = (NN * 64 + 255) / 256;
    dim3 ggrid((NN + 127) / 128, KP / KGRP);
    const int egrid = (EE * 16 + 255) / 256;
    const int fgrid = (NN + 7) / 8;

    init_kernel<<<zgrid, 256>>>();
    prep_kernel<<<(EE + 255) / 256, 256>>>(ei, ea);
    recip_kernel<<<(NN + 255) / 256, 256>>>();
    scale_kernel<<<(EE + 255) / 256, 256>>>();

    // ---- layer 0 (cin = 32) ----
    gemm_y_h<C0><<<ggrid, 256, smem0>>>(x, w0);
    edge_kernel<<<egrid, 256>>>();
    finalize_kernel<C0><<<fgrid, 512>>>(x, root0, b0, h1p);

    // ---- layer 1 (cin = 64) ----
    gemm_y_h<C1><<<ggrid, 256, smem1>>>(h1p, w1);
    edge_kernel<<<egrid, 256>>>();
    finalize_kernel<C1><<<fgrid, 512>>>(h1p, root1, b1, h2p);

    // ---- final fused concat-GEMM ----
    final_kernel<<<fgrid, 512>>>(x, fw, fb, out);
}

// round 15
// speedup vs baseline: 1.5844x; 1.0075x over previous
#include <cuda_runtime.h>
#include <cuda_fp16.h>
#include <math.h>
#include <stdint.h>

#define NN 50000
#define EE 800000
#define C0 32
#define C1 64
#define KP 25
#define KGRP 5
#define FIN 160
#define YSTRIDE (KP * 64)   // 1600
#define CSW 72              // C-staging stride in halfs (144 B)

// ---------------- scratch -----------------------------------------------------
__device__ __align__(16) __half g_Yh[(size_t)NN * YSTRIDE];  // 160 MB fp16
__device__ __align__(16) float  g_H1[(size_t)NN * 64];
__device__ __align__(16) float  g_H2[(size_t)NN * 64];
__device__ __align__(16) float  g_AGG[(size_t)NN * 64];
__device__ __align__(16) float  g_DEG[NN];                   // count -> 1/max(deg,1)
__device__ __align__(16) float4 g_B[EE];                     // basis pre-scaled by 1/deg
__device__ int    g_K0[EE];
__device__ int    g_src[EE];
__device__ int    g_dst[EE];

// ---------------- init / degcnt / recip / prep -------------------------------
__global__ void init_kernel() {
    int i = blockIdx.x * blockDim.x + threadIdx.x;
    if (i < NN * 64) g_AGG[i] = 0.0f;
    if (i < NN)      g_DEG[i] = 0.0f;
}

__global__ void degcnt_kernel(const int* __restrict__ ei) {
    int e = blockIdx.x * blockDim.x + threadIdx.x;
    if (e >= EE) return;
    atomicAdd(&g_DEG[ei[EE + e]], 1.0f);
}

__global__ void recip_kernel() {
    int i = blockIdx.x * blockDim.x + threadIdx.x;
    if (i < NN) g_DEG[i] = 1.0f / fmaxf(g_DEG[i], 1.0f);
}

// basis + knot index + endpoints; basis pre-scaled by 1/deg(dst) (g_B written once)
__global__ void prep_kernel(const int* __restrict__ ei,
                            const float* __restrict__ ea) {
    int e = blockIdx.x * blockDim.x + threadIdx.x;
    if (e >= EE) return;
    int dst = ei[EE + e];
    g_src[e] = ei[e];
    g_dst[e] = dst;
    float inv = __ldg(&g_DEG[dst]);
    float v0 = ea[2 * e + 0] * 4.0f;
    float v1 = ea[2 * e + 1] * 4.0f;
    float b0f = floorf(v0), b1f = floorf(v1);
    float f0 = v0 - b0f, f1 = v1 - b1f;
    int i0 = min((int)b0f, 3);
    int i1 = min((int)b1f, 3);
    g_K0[e] = i0 + 5 * i1;
    g_B[e] = make_float4((1.f - f0) * (1.f - f1) * inv,
                         f0 * (1.f - f1) * inv,
                         (1.f - f0) * f1 * inv,
                         f0 * f1 * inv);
}

// ---------------- mma / ldmatrix / stmatrix helpers ---------------------------
__device__ __forceinline__ uint32_t pack_h2(float a, float b) {
    uint32_t r;
    asm("cvt.rn.f16x2.f32 %0, %1, %2;" : "=r"(r) : "f"(b), "f"(a));
    return r;
}

__device__ __forceinline__ void mma_f16(float c[4], const uint32_t a[4],
                                        const uint32_t b[2]) {
    asm volatile(
        "mma.sync.aligned.m16n8k16.row.col.f32.f16.f16.f32 "
        "{%0,%1,%2,%3}, {%4,%5,%6,%7}, {%8,%9}, {%0,%1,%2,%3};\n"
        : "+f"(c[0]), "+f"(c[1]), "+f"(c[2]), "+f"(c[3])
        : "r"(a[0]), "r"(a[1]), "r"(a[2]), "r"(a[3]),
          "r"(b[0]), "r"(b[1]));
}

__device__ __forceinline__ void ldsm_x4(uint32_t r[4], uint32_t addr) {
    asm volatile("ldmatrix.sync.aligned.m8n8.x4.shared.b16 {%0,%1,%2,%3}, [%4];"
                 : "=r"(r[0]), "=r"(r[1]), "=r"(r[2]), "=r"(r[3]) : "r"(addr));
}

__device__ __forceinline__ void ldsm_x2t(uint32_t r[2], uint32_t addr) {
    asm volatile("ldmatrix.sync.aligned.m8n8.x2.trans.shared.b16 {%0,%1}, [%2];"
                 : "=r"(r[0]), "=r"(r[1]) : "r"(addr));
}

__device__ __forceinline__ void stsm_x4(uint32_t addr, uint32_t r0, uint32_t r1,
                                        uint32_t r2, uint32_t r3) {
    asm volatile("stmatrix.sync.aligned.m8n8.x4.shared.b16 [%0], {%1,%2,%3,%4};"
                 :: "r"(addr), "r"(r0), "r"(r1), "r"(r2), "r"(r3));
}

// ---------------- Y = X @ W[k]; stmatrix-staged coalesced Y stores -----------
template <int CIN>
__global__ void __launch_bounds__(256)
gemm_y_h(const float* __restrict__ X, const float* __restrict__ W) {
    constexpr int SW  = CIN / 2 + 4;
    constexpr int WSW = 36;
    constexpr int KS  = CIN / 16;
    constexpr int NJ  = CIN / 16;
    extern __shared__ uint32_t sh[];
    uint32_t* Xs = sh;
    uint32_t* Ws = sh + 128 * SW;
    __half*   Cs = (__half*)(Ws + 2 * CIN * WSW);

    const int tid  = threadIdx.x;
    const int lane = tid & 31;
    const int wid  = tid >> 5;
    const int rowB = (wid >> 1) * 32;
    const int colB = (wid & 1) * 32;
    const int n0   = blockIdx.x * 128;
    const int kb   = blockIdx.y * KGRP;

    for (int i = tid; i < 128 * (CIN / 4); i += 256) {
        int r  = i / (CIN / 4);
        int c4 = (i % (CIN / 4)) * 4;
        float4 v = make_float4(0.f, 0.f, 0.f, 0.f);
        if (n0 + r < NN)
            v = __ldg((const float4*)(X + (size_t)(n0 + r) * CIN + c4));
        *(uint2*)&Xs[r * SW + c4 / 2] =
            make_uint2(pack_h2(v.x, v.y), pack_h2(v.z, v.w));
    }
    float4 wreg[NJ];
    {
        const float4* Wp = (const float4*)(W + (size_t)kb * CIN * 64);
        #pragma unroll
        for (int j = 0; j < NJ; j++) wreg[j] = __ldg(Wp + tid + j * 256);
    }
    __syncthreads();

    uint32_t a[2][KS][4];
    #pragma unroll
    for (int mt = 0; mt < 2; mt++)
        #pragma unroll
        for (int ks = 0; ks < KS; ks++) {
            int m  = rowB + mt * 16 + (lane & 15);
            int kw = ks * 8 + (lane >> 4) * 4;
            uint32_t addr = (uint32_t)__cvta_generic_to_shared(&Xs[m * SW + kw]);
            ldsm_x4(a[mt][ks], addr);
        }

    #pragma unroll
    for (int j = 0; j < NJ; j++) {
        int lin = (tid + j * 256) * 4;
        int kin = lin / 64, nn = lin % 64;
        float4 v = wreg[j];
        *(uint2*)&Ws[kin * WSW + nn / 2] =
            make_uint2(pack_h2(v.x, v.y), pack_h2(v.z, v.w));
    }
    {
        const float4* Wp = (const float4*)(W + (size_t)(kb + 1) * CIN * 64);
        #pragma unroll
        for (int j = 0; j < NJ; j++) wreg[j] = __ldg(Wp + tid + j * 256);
    }
    __syncthreads();

    const int st_t  = lane >> 3;
    const int st_rr = lane & 7;

    #pragma unroll
    for (int kk = 0; kk < KGRP; kk++) {
        const int k = kb + kk;
        if (kk + 1 < KGRP) {
            uint32_t* wnext = Ws + ((kk + 1) & 1) * CIN * WSW;
            #pragma unroll
            for (int j = 0; j < NJ; j++) {
                int lin = (tid + j * 256) * 4;
                int kin = lin / 64, nn = lin % 64;
                float4 v = wreg[j];
                *(uint2*)&wnext[kin * WSW + nn / 2] =
                    make_uint2(pack_h2(v.x, v.y), pack_h2(v.z, v.w));
            }
            if (kk + 2 < KGRP) {
                const float4* Wp = (const float4*)(W + (size_t)(k + 2) * CIN * 64);
                #pragma unroll
                for (int j = 0; j < NJ; j++) wreg[j] = __ldg(Wp + tid + j * 256);
            }
        }

        float c[2][4][4];
        #pragma unroll
        for (int mt = 0; mt < 2; mt++)
            #pragma unroll
            for (int nt = 0; nt < 4; nt++)
                #pragma unroll
                for (int q = 0; q < 4; q++) c[mt][nt][q] = 0.f;

        const uint32_t* wbuf = Ws + (kk & 1) * CIN * WSW;
        #pragma unroll
        for (int nt = 0; nt < 4; nt++) {
            #pragma unroll
            for (int ks = 0; ks < KS; ks++) {
                uint32_t b[2];
                int kr = ks * 16 + (lane & 15);
                uint32_t addr = (uint32_t)__cvta_generic_to_shared(
                    &wbuf[kr * WSW + (colB + nt * 8) / 2]);
                ldsm_x2t(b, addr);
                mma_f16(c[0][nt], a[0][ks], b);
                mma_f16(c[1][nt], a[1][ks], b);
            }
        }

        #pragma unroll
        for (int mt = 0; mt < 2; mt++) {
            #pragma unroll
            for (int np = 0; np < 2; np++) {
                int row = rowB + mt * 16 + ((st_t & 1) ? 8 : 0) + st_rr;
                int col = colB + np * 16 + (st_t >> 1) * 8;
                uint32_t addr = (uint32_t)__cvta_generic_to_shared(
                    &Cs[row * CSW + col]);
                stsm_x4(addr,
                        pack_h2(c[mt][np * 2 + 0][0], c[mt][np * 2 + 0][1]),
                        pack_h2(c[mt][np * 2 + 0][2], c[mt][np * 2 + 0][3]),
                        pack_h2(c[mt][np * 2 + 1][0], c[mt][np * 2 + 1][1]),
                        pack_h2(c[mt][np * 2 + 1][2], c[mt][np * 2 + 1][3]));
            }
        }
        __syncthreads();

        #pragma unroll
        for (int j = 0; j < 4; j++) {
            int idx = tid + j * 256;
            int row = idx >> 3;
            int seg = idx & 7;
            uint4 v = *(uint4*)&Cs[row * CSW + seg * 8];
            if (n0 + row < NN)
                *(uint4*)&g_Yh[(size_t)(n0 + row) * YSTRIDE + k * 64 + seg * 8] = v;
        }
        __syncthreads();
    }
}

// ---------------- per-edge gather: 8 lanes/edge, LDG.128, 2x RED.128 ---------
__global__ void edge_kernel() {
    int t = blockIdx.x * blockDim.x + threadIdx.x;
    int e = t >> 3;
    int lane = t & 7;
    if (e >= EE) return;

    int src = g_src[e];
    int dst = g_dst[e];
    int k0  = g_K0[e];
    float4 b = g_B[e];   // pre-scaled by 1/deg(dst)

    // one Y row = 64 halfs = 8 uint4; each lane owns 8 consecutive channels
    const uint4* base = (const uint4*)(g_Yh + (size_t)src * YSTRIDE + k0 * 64);
    uint4 q0 = __ldg(base + lane);        // row k0
    uint4 q1 = __ldg(base + 8 + lane);    // row k0+1
    uint4 q2 = __ldg(base + 40 + lane);   // row k0+5
    uint4 q3 = __ldg(base + 48 + lane);   // row k0+6

    float m[8];
    {
        const uint32_t* p0 = &q0.x;
        const uint32_t* p1 = &q1.x;
        const uint32_t* p2 = &q2.x;
        const uint32_t* p3 = &q3.x;
        #pragma unroll
        for (int j = 0; j < 4; j++) {
            float2 r0 = __half22float2(*(__half2*)&p0[j]);
            float2 r1 = __half22float2(*(__half2*)&p1[j]);
            float2 r2 = __half22float2(*(__half2*)&p2[j]);
            float2 r3 = __half22float2(*(__half2*)&p3[j]);
            m[2 * j + 0] = b.x * r0.x + b.y * r1.x + b.z * r2.x + b.w * r3.x;
            m[2 * j + 1] = b.x * r0.y + b.y * r1.y + b.z * r2.y + b.w * r3.y;
        }
    }

    float* dptr = g_AGG + (size_t)dst * 64 + lane * 8;
    asm volatile("red.global.add.v4.f32 [%0], {%1, %2, %3, %4};"
                 :: "l"(dptr), "f"(m[0]), "f"(m[1]), "f"(m[2]), "f"(m[3])
                 : "memory");
    asm volatile("red.global.add.v4.f32 [%0], {%1, %2, %3, %4};"
                 :: "l"(dptr + 4), "f"(m[4]), "f"(m[5]), "f"(m[6]), "f"(m[7])
                 : "memory");
}

// ---------------- finalize: 8 nodes/block (round-9 configuration) ------------
template <int CIN>
__global__ void finalize_kernel(const float* __restrict__ X,
                                const float* __restrict__ root,
                                const float* __restrict__ bias,
                                float* __restrict__ H) {
    __shared__ __align__(16) float rs[CIN * 64];
    __shared__ __align__(16) float xs[8][CIN];
    const int tid = threadIdx.x;

    for (int i = tid; i < CIN * 16; i += 512)
        ((float4*)rs)[i] = __ldg(((const float4*)root) + i);

    const int n0 = blockIdx.x * 8;
    for (int i = tid; i < 8 * CIN / 4; i += 512) {
        int lin = i * 4;
        int r = lin / CIN, c = lin % CIN;
        int n = n0 + r;
        float4 v = make_float4(0.f, 0.f, 0.f, 0.f);
        if (n < NN) v = __ldg((const float4*)(X + (size_t)n * CIN + c));
        *(float4*)&xs[r][c] = v;
    }
    __syncthreads();

    const int ln = tid >> 6;
    const int o  = tid & 63;
    const int n  = n0 + ln;
    if (n >= NN) return;

    float acc = 0.f;
    #pragma unroll
    for (int i = 0; i < CIN; i++)
        acc = fmaf(xs[ln][i], rs[i * 64 + o], acc);

    size_t ai = (size_t)n * 64 + o;
    float v = g_AGG[ai] + acc + __ldg(bias + o);
    g_AGG[ai] = 0.0f;
    H[ai] = fmaxf(v, 0.0f);
}

// ---------------- final: concat(x,h1,h2) @ fw + fb (round-9 configuration) ---
__global__ void final_kernel(const float* __restrict__ X,
                             const float* __restrict__ fw,
                             const float* __restrict__ fb,
                             float* __restrict__ out) {
    __shared__ __align__(16) float ws[FIN * 64];
    __shared__ __align__(16) float xs[8][FIN];
    const int tid = threadIdx.x;

    for (int i = tid; i < FIN * 16; i += 512)
        ((float4*)ws)[i] = __ldg(((const float4*)fw) + i);

    const int n0 = blockIdx.x * 8;
    for (int i = tid; i < 8 * FIN / 4; i += 512) {
        int lin = i * 4;
        int r = lin / FIN, c = lin % FIN;
        int n = n0 + r;
        float4 v = make_float4(0.f, 0.f, 0.f, 0.f);
        if (n < NN) {
            if (c < 32)      v = __ldg((const float4*)(X    + (size_t)n * 32 + c));
            else if (c < 96) v = __ldg((const float4*)(g_H1 + (size_t)n * 64 + (c - 32)));
            else             v = __ldg((const float4*)(g_H2 + (size_t)n * 64 + (c - 96)));
        }
        *(float4*)&xs[r][c] = v;
    }
    __syncthreads();

    const int ln = tid >> 6;
    const int o  = tid & 63;
    const int n  = n0 + ln;
    if (n >= NN) return;

    float acc = __ldg(fb + o);
    #pragma unroll
    for (int i = 0; i < FIN; i++)
        acc = fmaf(xs[ln][i], ws[i * 64 + o], acc);
    out[(size_t)n * 64 + o] = acc;
}

// ---------------- launch -----------------------------------------------------
extern "C" void kernel_launch(void* const* d_in, const int* in_sizes, int n_in,
                              void* d_out, int out_size) {
    const float* x     = (const float*)d_in[0];
    const int*   ei    = (const int*)d_in[1];     // int32 (jax x64 disabled)
    const float* ea    = (const float*)d_in[2];
    const float* w0    = (const float*)d_in[3];
    const float* root0 = (const float*)d_in[4];
    const float* b0    = (const float*)d_in[5];
    const float* w1    = (const float*)d_in[6];
    const float* root1 = (const float*)d_in[7];
    const float* b1    = (const float*)d_in[8];
    const float* fw    = (const float*)d_in[9];
    const float* fb    = (const float*)d_in[10];
    float*       out   = (float*)d_out;

    float *h1p, *h2p;
    cudaGetSymbolAddress((void**)&h1p, g_H1);
    cudaGetSymbolAddress((void**)&h2p, g_H2);

    const int smem0 = (128 * (C0 / 2 + 4) + 2 * C0 * 36) * 4 + 128 * CSW * 2;
    const int smem1 = (128 * (C1 / 2 + 4) + 2 * C1 * 36) * 4 + 128 * CSW * 2;
    cudaFuncSetAttribute(gemm_y_h<C0>, cudaFuncAttributeMaxDynamicSharedMemorySize, smem0);
    cudaFuncSetAttribute(gemm_y_h<C1>, cudaFuncAttributeMaxDynamicSharedMemorySize, smem1);

    const int zgrid = (NN * 64 + 255) / 256;
    dim3 ggrid((NN + 127) / 128, KP / KGRP);
    const int egrid = (EE * 8 + 255) / 256;
    const int fgrid = (NN + 7) / 8;

    init_kernel<<<zgrid, 256>>>();
    degcnt_kernel<<<(EE + 255) / 256, 256>>>(ei);
    recip_kernel<<<(NN + 255) / 256, 256>>>();
    prep_kernel<<<(EE + 255) / 256, 256>>>(ei, ea);

    // ---- layer 0 (cin = 32) ----
    gemm_y_h<C0><<<ggrid, 256, smem0>>>(x, w0);
    edge_kernel<<<egrid, 256>>>();
    finalize_kernel<C0><<<fgrid, 512>>>(x, root0, b0, h1p);

    // ---- layer 1 (cin = 64) ----
    gemm_y_h<C1><<<ggrid, 256, smem1>>>(h1p, w1);
    edge_kernel<<<egrid, 256>>>();
    finalize_kernel<C1><<<fgrid, 512>>>(h1p, root1, b1, h2p);

    // ---- final fused concat-GEMM ----
    final_kernel<<<fgrid, 512>>>(x, fw, fb, out);
}